// round 5
// baseline (speedup 1.0000x reference)
#include <cuda_runtime.h>
#include <cuda_bf16.h>
#include <math.h>
#include <stdint.h>

#define DMODEL 2048
#define NHEADS 16
#define DHEAD  128
#define SEQ    2048
#define BATCH  2
#define BHN    (BATCH*NHEADS)   // 32
#define MROWS  (BATCH*SEQ)      // 4096

// log2(e) / sqrt(128)
#define QSCALE (1.4426950408889634f * 0.08838834764831845f)

// ---- pipelined HMMA GEMM config: CTA 128x128, KBLK 32, 2-stage cp.async ----
#define KBLK2  32
#define NIT    (DMODEL / KBLK2)    // 64
#define SROW   80                  // bytes per smem row (32 bf16 data + 8 pad)
#define GTILE  (128 * SROW)        // 10240
#define GSTAGE (4 * GTILE)         // 40960 (Ah, Al, Bh, Bl)
#define GEMM_SMEM (2 * GSTAGE)     // 81920

// ---- HMMA flash config: 128 q x 128 kv, stride 272 B ----
#define FS   272
#define FT   (128 * FS)
#define FQH  0
#define FQL  (FT)
#define FKH  (2*FT)
#define FKL  (3*FT)
#define FVH  (4*FT)
#define FVL  (5*FT)
#define FLASH_SMEM (6*FT)          // 208896 B

// ---------------- scratch (device globals; allocation-free) ----------------
__device__ float  g_q[(size_t)BHN * SEQ * DHEAD];
__device__ float  g_k[(size_t)BHN * SEQ * DHEAD];
__device__ float2 g_rope[SEQ * 64];

__device__ __nv_bfloat16 g_ah[(size_t)MROWS * DMODEL];
__device__ __nv_bfloat16 g_al[(size_t)MROWS * DMODEL];
__device__ __nv_bfloat16 g_wqh[(size_t)DMODEL * DMODEL];
__device__ __nv_bfloat16 g_wql[(size_t)DMODEL * DMODEL];
__device__ __nv_bfloat16 g_wkh[(size_t)DMODEL * DMODEL];
__device__ __nv_bfloat16 g_wkl[(size_t)DMODEL * DMODEL];
__device__ __nv_bfloat16 g_wvh[(size_t)DMODEL * DMODEL];
__device__ __nv_bfloat16 g_wvl[(size_t)DMODEL * DMODEL];
__device__ __nv_bfloat16 g_woh[(size_t)DMODEL * DMODEL];
__device__ __nv_bfloat16 g_wol[(size_t)DMODEL * DMODEL];

__device__ __nv_bfloat16 g_qh[(size_t)BHN * SEQ * DHEAD];
__device__ __nv_bfloat16 g_ql[(size_t)BHN * SEQ * DHEAD];
__device__ __nv_bfloat16 g_kh[(size_t)BHN * SEQ * DHEAD];
__device__ __nv_bfloat16 g_kl[(size_t)BHN * SEQ * DHEAD];
__device__ __nv_bfloat16 g_vh[(size_t)BHN * SEQ * DHEAD];
__device__ __nv_bfloat16 g_vl[(size_t)BHN * SEQ * DHEAD];

// ---------------- helpers ----------------
__device__ __forceinline__ void ldsm4(uint32_t* r, uint32_t addr) {
    asm volatile("ldmatrix.sync.aligned.m8n8.x4.shared.b16 {%0,%1,%2,%3}, [%4];"
                 : "=r"(r[0]), "=r"(r[1]), "=r"(r[2]), "=r"(r[3]) : "r"(addr));
}
__device__ __forceinline__ void ldsm4t(uint32_t* r, uint32_t addr) {
    asm volatile("ldmatrix.sync.aligned.m8n8.x4.trans.shared.b16 {%0,%1,%2,%3}, [%4];"
                 : "=r"(r[0]), "=r"(r[1]), "=r"(r[2]), "=r"(r[3]) : "r"(addr));
}
__device__ __forceinline__ void mma16816(float* d, const uint32_t* a,
                                         uint32_t b0, uint32_t b1) {
    asm volatile(
        "mma.sync.aligned.m16n8k16.row.col.f32.bf16.bf16.f32 "
        "{%0,%1,%2,%3}, {%4,%5,%6,%7}, {%8,%9}, {%0,%1,%2,%3};"
        : "+f"(d[0]), "+f"(d[1]), "+f"(d[2]), "+f"(d[3])
        : "r"(a[0]), "r"(a[1]), "r"(a[2]), "r"(a[3]), "r"(b0), "r"(b1));
}
__device__ __forceinline__ float ex2(float x) {
    float y; asm("ex2.approx.f32 %0, %1;" : "=f"(y) : "f"(x)); return y;
}
__device__ __forceinline__ uint32_t packbf(float lo, float hi) {
    uint32_t r; asm("cvt.rn.bf16x2.f32 %0, %1, %2;" : "=r"(r) : "f"(hi), "f"(lo));
    return r;
}
__device__ __forceinline__ void cpasync16(uint32_t s, const void* g) {
    asm volatile("cp.async.cg.shared.global [%0], [%1], 16;" :: "r"(s), "l"(g));
}

// ---------------------------------------------------------------------------
// RoPE table (fp32 angle, fp64 sin/cos)
// ---------------------------------------------------------------------------
__global__ void rope_table_kernel() {
    int p = blockIdx.x;
    int i = threadIdx.x;  // 0..63
    float freq = (float)pow(10000.0, (double)i / 64.0);
    float ang  = (float)p / freq;
    double s, c;
    sincos((double)ang, &s, &c);
    g_rope[p * 64 + i] = make_float2((float)s, (float)c);
}

// ---------------------------------------------------------------------------
// Rope + bf16 hi/lo split for q (QSCALE folded) and k.
// ---------------------------------------------------------------------------
__global__ void rope_split_kernel() {
    int gid = blockIdx.x * 256 + threadIdx.x;
    int i    = gid & 63;
    int rest = gid >> 6;
    int p    = rest & 2047;
    int bh   = rest >> 11;
    float2 sc = g_rope[p * 64 + i];
    size_t base = ((size_t)bh * SEQ + p) * DHEAD;

    float x0 = g_q[base + i], x1 = g_q[base + 64 + i];
    float q0 = (x0 * sc.y - x1 * sc.x) * QSCALE;
    float q1 = (x1 * sc.y + x0 * sc.x) * QSCALE;
    float y0 = g_k[base + i], y1 = g_k[base + 64 + i];
    float k0 = y0 * sc.y - y1 * sc.x;
    float k1 = y1 * sc.y + y0 * sc.x;

    __nv_bfloat16 h;
    h = __float2bfloat16(q0); g_qh[base + i]      = h; g_ql[base + i]      = __float2bfloat16(q0 - __bfloat162float(h));
    h = __float2bfloat16(q1); g_qh[base + 64 + i] = h; g_ql[base + 64 + i] = __float2bfloat16(q1 - __bfloat162float(h));
    h = __float2bfloat16(k0); g_kh[base + i]      = h; g_kl[base + i]      = __float2bfloat16(k0 - __bfloat162float(h));
    h = __float2bfloat16(k1); g_kh[base + 64 + i] = h; g_kl[base + 64 + i] = __float2bfloat16(k1 - __bfloat162float(h));
}

// ---------------------------------------------------------------------------
// fp32 -> (bf16 hi, bf16 lo) split, elementwise.
// ---------------------------------------------------------------------------
__global__ void split_kernel(const float* __restrict__ x,
                             __nv_bfloat16* __restrict__ hi,
                             __nv_bfloat16* __restrict__ lo) {
    size_t i = ((size_t)blockIdx.x * 256 + threadIdx.x) * 4;
    float4 v = *(const float4*)(x + i);
    float a[4] = {v.x, v.y, v.z, v.w};
    uint32_t ph[2], pl[2];
#pragma unroll
    for (int j = 0; j < 2; ++j) {
        __nv_bfloat16 h0 = __float2bfloat16(a[2*j]);
        __nv_bfloat16 h1 = __float2bfloat16(a[2*j+1]);
        __nv_bfloat16 l0 = __float2bfloat16(a[2*j]   - __bfloat162float(h0));
        __nv_bfloat16 l1 = __float2bfloat16(a[2*j+1] - __bfloat162float(h1));
        ph[j] = (uint32_t)__bfloat16_as_ushort(h0) | ((uint32_t)__bfloat16_as_ushort(h1) << 16);
        pl[j] = (uint32_t)__bfloat16_as_ushort(l0) | ((uint32_t)__bfloat16_as_ushort(l1) << 16);
    }
    *(uint2*)((char*)hi + i * 2) = make_uint2(ph[0], ph[1]);
    *(uint2*)((char*)lo + i * 2) = make_uint2(pl[0], pl[1]);
}

// ---------------------------------------------------------------------------
// Transpose + split: src [H][R][C] fp32 -> dst[h*C + c][r] bf16 (hi, lo).
// ---------------------------------------------------------------------------
__global__ void transpose_split_kernel(const float* __restrict__ src,
                                       __nv_bfloat16* __restrict__ hi,
                                       __nv_bfloat16* __restrict__ lo,
                                       int R, int C) {
    __shared__ float t[32][33];
    int h  = blockIdx.z;
    int r0 = blockIdx.y << 5, c0 = blockIdx.x << 5;
    int tx = threadIdx.x, ty = threadIdx.y;  // 32 x 8
    const float* s = src + (size_t)h * R * C;
#pragma unroll
    for (int j = 0; j < 4; ++j)
        t[ty + 8 * j][tx] = s[(size_t)(r0 + ty + 8 * j) * C + c0 + tx];
    __syncthreads();
#pragma unroll
    for (int j = 0; j < 4; ++j) {
        int c = c0 + ty + 8 * j;
        float v = t[tx][ty + 8 * j];
        __nv_bfloat16 vh = __float2bfloat16(v);
        __nv_bfloat16 vl = __float2bfloat16(v - __bfloat162float(vh));
        size_t o = (size_t)(h * C + c) * R + r0 + tx;
        hi[o] = vh;
        lo[o] = vl;
    }
}

// issue one k-block's cp.async loads into stage buffer `buf`
#define GEMM_ISSUE(it, buf) do {                                              \
    const int _k0 = (it) * KBLK2;                                             \
    const uint32_t _sd = sb + (uint32_t)(buf) * GSTAGE;                       \
    _Pragma("unroll")                                                         \
    for (int _sl = 0; _sl < 2; ++_sl) {                                       \
        int _slot = tid + _sl * 256;                                          \
        int _r  = _slot >> 2;                                                 \
        int _cb = (_slot & 3) * 16;                                           \
        size_t _ga = ((size_t)(row0 + _r) * DMODEL + _k0) * 2 + _cb;          \
        size_t _gb = ((size_t)(n0   + _r) * DMODEL + _k0) * 2 + _cb;          \
        uint32_t _so = _sd + (uint32_t)(_r * SROW + _cb);                     \
        cpasync16(_so,             pAh + _ga);                                \
        cpasync16(_so + GTILE,     pAl + _ga);                                \
        cpasync16(_so + 2*GTILE,   pBh + _gb);                                \
        cpasync16(_so + 3*GTILE,   pBl + _gb);                                \
    }                                                                         \
    asm volatile("cp.async.commit_group;" ::: "memory");                      \
} while (0)

// ---------------------------------------------------------------------------
// Pipelined HMMA split GEMM: out = A * B^T + bias. 2-stage cp.async, KBLK=32.
// mode 0: fp32 out -> [b][h][p][e]; mode 1: fp32 row-major;
// mode 2: bf16 hi/lo split out -> outh/outl at [b][h][p][e]  (V path).
// ---------------------------------------------------------------------------
__global__ __launch_bounds__(256, 2) void gemm_hmma(
    const __nv_bfloat16* __restrict__ Ah,
    const __nv_bfloat16* __restrict__ Al,
    const __nv_bfloat16* __restrict__ Bh,
    const __nv_bfloat16* __restrict__ Bl,
    const float* __restrict__ bias,
    float* __restrict__ out,
    __nv_bfloat16* __restrict__ outh,
    __nv_bfloat16* __restrict__ outl,
    int mode)
{
    extern __shared__ char sm[];
    const uint32_t sb = (uint32_t)__cvta_generic_to_shared(sm);

    const int tid  = threadIdx.x;
    const int wid  = tid >> 5;
    const int lane = tid & 31;
    const int row0 = blockIdx.y * 128;
    const int n0   = blockIdx.x * 128;
    const int m_w  = (wid >> 2) * 64;
    const int n_w  = (wid & 3) * 32;

    const char* pAh = (const char*)Ah;
    const char* pAl = (const char*)Al;
    const char* pBh = (const char*)Bh;
    const char* pBl = (const char*)Bl;

    const uint32_t aOff = (uint32_t)(m_w + (lane & 15)) * SROW + ((lane >> 4) << 4);
    const uint32_t bOff = (uint32_t)(n_w + ((lane >> 4) << 3) + (lane & 7)) * SROW +
                          (uint32_t)((lane & 8) << 1);

    float acc[4][4][4];
#pragma unroll
    for (int i = 0; i < 4; ++i)
#pragma unroll
        for (int j = 0; j < 4; ++j)
#pragma unroll
            for (int r = 0; r < 4; ++r) acc[i][j][r] = 0.0f;

    GEMM_ISSUE(0, 0);

    for (int it = 0; it < NIT; ++it) {
        if (it + 1 < NIT) {
            GEMM_ISSUE(it + 1, (it + 1) & 1);
            asm volatile("cp.async.wait_group 1;" ::: "memory");
        } else {
            asm volatile("cp.async.wait_group 0;" ::: "memory");
        }
        __syncthreads();

        const uint32_t bufo = (uint32_t)(it & 1) * GSTAGE;
        const uint32_t aHi = sb + bufo + aOff;
        const uint32_t aLo = aHi + GTILE;
        const uint32_t bHi = sb + bufo + 2*GTILE + bOff;
        const uint32_t bLo = bHi + GTILE;

#pragma unroll
        for (int kk = 0; kk < 2; ++kk) {
            uint32_t Af[4][4], Bf[2][4];
#pragma unroll
            for (int mi = 0; mi < 4; ++mi)
                ldsm4(Af[mi], aHi + mi * (16 * SROW) + kk * 32);
#pragma unroll
            for (int ni = 0; ni < 2; ++ni)
                ldsm4(Bf[ni], bHi + ni * (16 * SROW) + kk * 32);
#pragma unroll
            for (int mi = 0; mi < 4; ++mi)
#pragma unroll
                for (int j = 0; j < 4; ++j)
                    mma16816(acc[mi][j], Af[mi], Bf[j >> 1][(j & 1) * 2],
                             Bf[j >> 1][(j & 1) * 2 + 1]);
            {
                uint32_t Al4[4];
#pragma unroll
                for (int mi = 0; mi < 4; ++mi) {
                    ldsm4(Al4, aLo + mi * (16 * SROW) + kk * 32);
#pragma unroll
                    for (int j = 0; j < 4; ++j)
                        mma16816(acc[mi][j], Al4, Bf[j >> 1][(j & 1) * 2],
                                 Bf[j >> 1][(j & 1) * 2 + 1]);
                }
            }
#pragma unroll
            for (int ni = 0; ni < 2; ++ni)
                ldsm4(Bf[ni], bLo + ni * (16 * SROW) + kk * 32);
#pragma unroll
            for (int mi = 0; mi < 4; ++mi)
#pragma unroll
                for (int j = 0; j < 4; ++j)
                    mma16816(acc[mi][j], Af[mi], Bf[j >> 1][(j & 1) * 2],
                             Bf[j >> 1][(j & 1) * 2 + 1]);
        }
        __syncthreads();
    }

    // Epilogue
    const int g = lane >> 2, t4 = lane & 3;
#pragma unroll
    for (int mi = 0; mi < 4; ++mi) {
        int m = row0 + m_w + mi * 16 + g;
#pragma unroll
        for (int j = 0; j < 4; ++j) {
            int col = n0 + n_w + j * 8 + t4 * 2;
            float b0 = bias[col], b1 = bias[col + 1];
            float2 v0 = make_float2(acc[mi][j][0] + b0, acc[mi][j][1] + b1);
            float2 v1 = make_float2(acc[mi][j][2] + b0, acc[mi][j][3] + b1);
            if (mode == 1) {
                *(float2*)(out + (size_t)m * DMODEL + col)       = v0;
                *(float2*)(out + (size_t)(m + 8) * DMODEL + col) = v1;
            } else {
                int h = col >> 7, e = col & 127;
                int b  = m >> 11, p = m & 2047;
                size_t base = (((size_t)(b * NHEADS + h) * SEQ) << 7) + e;
                size_t i0 = base + ((size_t)p << 7);
                size_t i1 = base + ((size_t)(p + 8) << 7);
                if (mode == 0) {
                    *(float2*)(out + i0) = v0;
                    *(float2*)(out + i1) = v1;
                } else {  // mode 2: bf16 hi/lo split (V path)
                    uint32_t h0 = packbf(v0.x, v0.y);
                    uint32_t l0 = packbf(v0.x - __uint_as_float(h0 << 16),
                                         v0.y - __uint_as_float(h0 & 0xffff0000u));
                    uint32_t h1 = packbf(v1.x, v1.y);
                    uint32_t l1 = packbf(v1.x - __uint_as_float(h1 << 16),
                                         v1.y - __uint_as_float(h1 & 0xffff0000u));
                    *(uint32_t*)(outh + i0) = h0;
                    *(uint32_t*)(outl + i0) = l0;
                    *(uint32_t*)(outh + i1) = h1;
                    *(uint32_t*)(outl + i1) = l1;
                }
            }
        }
    }
}

// ---------------------------------------------------------------------------
// HMMA causal flash attention. CTA = 128 q x 128 kv, 8 warps x 16 rows.
// Epilogue writes z directly as bf16 hi/lo into g_ah/g_al (O-proj input).
// ---------------------------------------------------------------------------
__global__ __launch_bounds__(256, 1) void flash_hmma() {
    extern __shared__ char sm[];
    const uint32_t sb = (uint32_t)__cvta_generic_to_shared(sm);

    const int tid  = threadIdx.x;
    const int wid  = tid >> 5;
    const int lane = tid & 31;
    const int bh   = blockIdx.y;
    const int qt   = gridDim.x - 1 - blockIdx.x;   // heavy tiles first
    const int q0   = qt * 128;

    const __nv_bfloat16* qh = g_qh + (size_t)bh * SEQ * DHEAD;
    const __nv_bfloat16* ql = g_ql + (size_t)bh * SEQ * DHEAD;
    const __nv_bfloat16* kh = g_kh + (size_t)bh * SEQ * DHEAD;
    const __nv_bfloat16* kl = g_kl + (size_t)bh * SEQ * DHEAD;
    const __nv_bfloat16* vh = g_vh + (size_t)bh * SEQ * DHEAD;
    const __nv_bfloat16* vl = g_vl + (size_t)bh * SEQ * DHEAD;

#pragma unroll
    for (int i = 0; i < 8; ++i) {
        int f = tid + i * 256;
        int r = f >> 4, c8 = (f & 15) * 8;
        uint32_t off = (uint32_t)(r * FS + c8 * 2);
        size_t g = (size_t)(q0 + r) * DHEAD + c8;
        *(uint4*)(sm + FQH + off) = *(const uint4*)(qh + g);
        *(uint4*)(sm + FQL + off) = *(const uint4*)(ql + g);
    }

    const uint32_t aOff = (uint32_t)(wid * 16 + (lane & 15)) * FS + ((lane >> 4) << 4);
    const uint32_t aQh = sb + FQH + aOff;
    const uint32_t aQl = sb + FQL + aOff;
    const uint32_t bOff = (uint32_t)(((lane >> 4) << 3) + (lane & 7)) * FS +
                          (uint32_t)((lane & 8) << 1);
    const uint32_t bKh = sb + FKH + bOff;
    const uint32_t bKl = sb + FKL + bOff;
    const uint32_t vOff = (uint32_t)(lane & 15) * FS + ((lane >> 4) << 4);
    const uint32_t bVh = sb + FVH + vOff;
    const uint32_t bVl = sb + FVL + vOff;

    float o[16][4];
#pragma unroll
    for (int j = 0; j < 16; ++j)
#pragma unroll
        for (int r = 0; r < 4; ++r) o[j][r] = 0.0f;
    float m1 = -1e30f, m2 = -1e30f, l1 = 0.0f, l2 = 0.0f;

    for (int t = 0; t <= qt; ++t) {
        const int k0 = t * 128;
        __syncthreads();
#pragma unroll
        for (int i = 0; i < 8; ++i) {
            int f = tid + i * 256;
            int r = f >> 4, c8 = (f & 15) * 8;
            uint32_t off = (uint32_t)(r * FS + c8 * 2);
            size_t g = (size_t)(k0 + r) * DHEAD + c8;
            *(uint4*)(sm + FKH + off) = *(const uint4*)(kh + g);
            *(uint4*)(sm + FKL + off) = *(const uint4*)(kl + g);
            *(uint4*)(sm + FVH + off) = *(const uint4*)(vh + g);
            *(uint4*)(sm + FVL + off) = *(const uint4*)(vl + g);
        }
        __syncthreads();

        float s[16][4];
#pragma unroll
        for (int j = 0; j < 16; ++j)
#pragma unroll
            for (int r = 0; r < 4; ++r) s[j][r] = 0.0f;

#pragma unroll
        for (int kk = 0; kk < 8; ++kk) {
            uint32_t qa[4], qb[4], kb[4];
            ldsm4(qa, aQh + kk * 32);
            ldsm4(qb, aQl + kk * 32);
#pragma unroll
            for (int nn = 0; nn < 8; ++nn) {
                ldsm4(kb, bKh + nn * (16 * FS) + kk * 32);
                mma16816(s[2*nn],   qa, kb[0], kb[1]);
                mma16816(s[2*nn+1], qa, kb[2], kb[3]);
                mma16816(s[2*nn],   qb, kb[0], kb[1]);
                mma16816(s[2*nn+1], qb, kb[2], kb[3]);
                ldsm4(kb, bKl + nn * (16 * FS) + kk * 32);
                mma16816(s[2*nn],   qa, kb[0], kb[1]);
                mma16816(s[2*nn+1], qa, kb[2], kb[3]);
            }
        }

        const int r1 = q0 + wid * 16 + (lane >> 2);
        const int r2 = r1 + 8;
        if (t == qt) {
            const int c0 = k0 + (lane & 3) * 2;
#pragma unroll
            for (int j = 0; j < 16; ++j) {
                int col = c0 + j * 8;
                if (col     > r1) s[j][0] = -1e30f;
                if (col + 1 > r1) s[j][1] = -1e30f;
                if (col     > r2) s[j][2] = -1e30f;
                if (col + 1 > r2) s[j][3] = -1e30f;
            }
        }

        float mx1 = -1e30f, mx2 = -1e30f;
#pragma unroll
        for (int j = 0; j < 16; ++j) {
            mx1 = fmaxf(mx1, fmaxf(s[j][0], s[j][1]));
            mx2 = fmaxf(mx2, fmaxf(s[j][2], s[j][3]));
        }
        mx1 = fmaxf(mx1, __shfl_xor_sync(0xffffffffu, mx1, 1));
        mx1 = fmaxf(mx1, __shfl_xor_sync(0xffffffffu, mx1, 2));
        mx2 = fmaxf(mx2, __shfl_xor_sync(0xffffffffu, mx2, 1));
        mx2 = fmaxf(mx2, __shfl_xor_sync(0xffffffffu, mx2, 2));
        float mn1 = fmaxf(m1, mx1), mn2 = fmaxf(m2, mx2);
        float sc1 = ex2(m1 - mn1), sc2 = ex2(m2 - mn2);
        float rs1 = 0.0f, rs2 = 0.0f;
#pragma unroll
        for (int j = 0; j < 16; ++j) {
            s[j][0] = ex2(s[j][0] - mn1);
            s[j][1] = ex2(s[j][1] - mn1);
            s[j][2] = ex2(s[j][2] - mn2);
            s[j][3] = ex2(s[j][3] - mn2);
            rs1 += s[j][0] + s[j][1];
            rs2 += s[j][2] + s[j][3];
        }
        rs1 += __shfl_xor_sync(0xffffffffu, rs1, 1);
        rs1 += __shfl_xor_sync(0xffffffffu, rs1, 2);
        rs2 += __shfl_xor_sync(0xffffffffu, rs2, 1);
        rs2 += __shfl_xor_sync(0xffffffffu, rs2, 2);
        l1 = l1 * sc1 + rs1;  m1 = mn1;
        l2 = l2 * sc2 + rs2;  m2 = mn2;
#pragma unroll
        for (int j = 0; j < 16; ++j) {
            o[j][0] *= sc1; o[j][1] *= sc1;
            o[j][2] *= sc2; o[j][3] *= sc2;
        }

#pragma unroll
        for (int kk = 0; kk < 8; ++kk) {
            uint32_t ph[4], pl[4], vb[4];
#pragma unroll
            for (int hv = 0; hv < 2; ++hv) {
                const float* sp = s[2*kk + hv];
                uint32_t p0 = packbf(sp[0], sp[1]);
                uint32_t p1 = packbf(sp[2], sp[3]);
                ph[hv*2]   = p0;
                ph[hv*2+1] = p1;
                pl[hv*2]   = packbf(sp[0] - __uint_as_float(p0 << 16),
                                    sp[1] - __uint_as_float(p0 & 0xffff0000u));
                pl[hv*2+1] = packbf(sp[2] - __uint_as_float(p1 << 16),
                                    sp[3] - __uint_as_float(p1 & 0xffff0000u));
            }
            uint32_t pha[4] = {ph[0], ph[1], ph[2], ph[3]};
            uint32_t pla[4] = {pl[0], pl[1], pl[2], pl[3]};
#pragma unroll
            for (int nn = 0; nn < 8; ++nn) {
                ldsm4t(vb, bVh + kk * (16 * FS) + nn * 32);
                mma16816(o[2*nn],   pha, vb[0], vb[1]);
                mma16816(o[2*nn+1], pha, vb[2], vb[3]);
                mma16816(o[2*nn],   pla, vb[0], vb[1]);
                mma16816(o[2*nn+1], pla, vb[2], vb[3]);
                ldsm4t(vb, bVl + kk * (16 * FS) + nn * 32);
                mma16816(o[2*nn],   pha, vb[0], vb[1]);
                mma16816(o[2*nn+1], pha, vb[2], vb[3]);
            }
        }
    }

    // Epilogue: normalize + bf16 hi/lo split straight into g_ah/g_al.
    const int b = bh >> 4, h = bh & 15;
    const int r1 = q0 + wid * 16 + (lane >> 2);
    const float inv1 = 1.0f / l1, inv2 = 1.0f / l2;
    size_t base1 = (size_t)(b * SEQ + r1) * DMODEL + h * DHEAD + (lane & 3) * 2;
    size_t base2 = base1 + (size_t)8 * DMODEL;
#pragma unroll
    for (int j = 0; j < 16; ++j) {
        float a0 = o[j][0] * inv1, a1 = o[j][1] * inv1;
        uint32_t hh = packbf(a0, a1);
        uint32_t ll = packbf(a0 - __uint_as_float(hh << 16),
                             a1 - __uint_as_float(hh & 0xffff0000u));
        *(uint32_t*)&g_ah[base1 + j * 8] = hh;
        *(uint32_t*)&g_al[base1 + j * 8] = ll;
        float a2 = o[j][2] * inv2, a3 = o[j][3] * inv2;
        uint32_t hh2 = packbf(a2, a3);
        uint32_t ll2 = packbf(a2 - __uint_as_float(hh2 << 16),
                              a3 - __uint_as_float(hh2 & 0xffff0000u));
        *(uint32_t*)&g_ah[base2 + j * 8] = hh2;
        *(uint32_t*)&g_al[base2 + j * 8] = ll2;
    }
}

// ---------------------------------------------------------------------------
extern "C" void kernel_launch(void* const* d_in, const int* in_sizes, int n_in,
                              void* d_out, int out_size) {
    (void)in_sizes; (void)n_in; (void)out_size;
    const float* qin = (const float*)d_in[0];
    const float* kin = (const float*)d_in[1];
    const float* vin = (const float*)d_in[2];
    const float* WQ  = (const float*)d_in[3];
    const float* WK  = (const float*)d_in[4];
    const float* WV  = (const float*)d_in[5];
    const float* WO  = (const float*)d_in[6];
    const float* bQ  = (const float*)d_in[7];
    const float* bK  = (const float*)d_in[8];
    const float* bV  = (const float*)d_in[9];
    const float* bO  = (const float*)d_in[10];
    float* out = (float*)d_out;

    float *pq, *pk;
    __nv_bfloat16 *ah, *al, *wqh, *wql, *wkh, *wkl, *wvh, *wvl, *woh, *wol, *vh, *vl;
    cudaGetSymbolAddress((void**)&pq, g_q);
    cudaGetSymbolAddress((void**)&pk, g_k);
    cudaGetSymbolAddress((void**)&ah, g_ah);
    cudaGetSymbolAddress((void**)&al, g_al);
    cudaGetSymbolAddress((void**)&wqh, g_wqh);
    cudaGetSymbolAddress((void**)&wql, g_wql);
    cudaGetSymbolAddress((void**)&wkh, g_wkh);
    cudaGetSymbolAddress((void**)&wkl, g_wkl);
    cudaGetSymbolAddress((void**)&wvh, g_wvh);
    cudaGetSymbolAddress((void**)&wvl, g_wvl);
    cudaGetSymbolAddress((void**)&woh, g_woh);
    cudaGetSymbolAddress((void**)&wol, g_wol);
    cudaGetSymbolAddress((void**)&vh, g_vh);
    cudaGetSymbolAddress((void**)&vl, g_vl);

    cudaFuncSetAttribute((const void*)gemm_hmma,
                         cudaFuncAttributeMaxDynamicSharedMemorySize, GEMM_SMEM);
    cudaFuncSetAttribute((const void*)flash_hmma,
                         cudaFuncAttributeMaxDynamicSharedMemorySize, FLASH_SMEM);

    rope_table_kernel<<<SEQ, 64>>>();

    dim3 tb(32, 8);
    transpose_split_kernel<<<dim3(4, 64, 16), tb>>>(WQ, wqh, wql, DMODEL, DHEAD);
    transpose_split_kernel<<<dim3(4, 64, 16), tb>>>(WK, wkh, wkl, DMODEL, DHEAD);
    transpose_split_kernel<<<dim3(4, 64, 16), tb>>>(WV, wvh, wvl, DMODEL, DHEAD);
    transpose_split_kernel<<<dim3(64, 64, 1), tb>>>(WO, woh, wol, DMODEL, DMODEL);

    dim3 ggrid(DMODEL / 128, MROWS / 128);
    const int nsplit = (MROWS * DMODEL) / (256 * 4);

    split_kernel<<<nsplit, 256>>>(qin, ah, al);
    gemm_hmma<<<ggrid, 256, GEMM_SMEM>>>(ah, al, wqh, wql, bQ, pq, 0, 0, 0);
    split_kernel<<<nsplit, 256>>>(kin, ah, al);
    gemm_hmma<<<ggrid, 256, GEMM_SMEM>>>(ah, al, wkh, wkl, bK, pk, 0, 0, 2 - 2);
    split_kernel<<<nsplit, 256>>>(vin, ah, al);
    gemm_hmma<<<ggrid, 256, GEMM_SMEM>>>(ah, al, wvh, wvl, bV, 0, vh, vl, 2);

    rope_split_kernel<<<(BHN * SEQ * 64) / 256, 256>>>();

    flash_hmma<<<dim3(SEQ / 128, BHN), 256, FLASH_SMEM>>>();  // -> g_ah/g_al

    gemm_hmma<<<ggrid, 256, GEMM_SMEM>>>(ah, al, woh, wol, bO, out, 0, 0, 1);
}

// round 6
// speedup vs baseline: 1.0721x; 1.0721x over previous
#include <cuda_runtime.h>
#include <cuda_bf16.h>
#include <math.h>
#include <stdint.h>

#define DMODEL 2048
#define NHEADS 16
#define DHEAD  128
#define SEQ    2048
#define BATCH  2
#define BHN    (BATCH*NHEADS)   // 32
#define MROWS  (BATCH*SEQ)      // 4096

// log2(e) / sqrt(128)
#define QSCALE (1.4426950408889634f * 0.08838834764831845f)

// ---- HMMA GEMM: CTA 128x128, KBLK 64, 4 warps (64x64 each), 128 threads ----
#define PADK 72                       // bf16 per smem row (144 B)
#define TILE_BYTES (128 * PADK * 2)   // 18432
#define OFF_AH 0
#define OFF_AL (TILE_BYTES)
#define OFF_BH (2*TILE_BYTES)
#define OFF_BL (3*TILE_BYTES)
#define GEMM_SMEM (4*TILE_BYTES)      // 73728 B

// ---- HMMA flash config: 128 q x 128 kv, stride 272 B ----
#define FS   272
#define FT   (128 * FS)
#define FQH  0
#define FQL  (FT)
#define FKH  (2*FT)
#define FKL  (3*FT)
#define FVH  (4*FT)
#define FVL  (5*FT)
#define FLASH_SMEM (6*FT)          // 208896 B

// ---------------- scratch (device globals; allocation-free) ----------------
__device__ float  g_q[(size_t)BHN * SEQ * DHEAD];
__device__ float  g_k[(size_t)BHN * SEQ * DHEAD];
__device__ float2 g_rope[SEQ * 64];

__device__ __nv_bfloat16 g_ah[(size_t)MROWS * DMODEL];
__device__ __nv_bfloat16 g_al[(size_t)MROWS * DMODEL];
__device__ __nv_bfloat16 g_wqh[(size_t)DMODEL * DMODEL];
__device__ __nv_bfloat16 g_wql[(size_t)DMODEL * DMODEL];
__device__ __nv_bfloat16 g_wkh[(size_t)DMODEL * DMODEL];
__device__ __nv_bfloat16 g_wkl[(size_t)DMODEL * DMODEL];
__device__ __nv_bfloat16 g_wvh[(size_t)DMODEL * DMODEL];
__device__ __nv_bfloat16 g_wvl[(size_t)DMODEL * DMODEL];
__device__ __nv_bfloat16 g_woh[(size_t)DMODEL * DMODEL];
__device__ __nv_bfloat16 g_wol[(size_t)DMODEL * DMODEL];

__device__ __nv_bfloat16 g_qh[(size_t)BHN * SEQ * DHEAD];
__device__ __nv_bfloat16 g_ql[(size_t)BHN * SEQ * DHEAD];
__device__ __nv_bfloat16 g_kh[(size_t)BHN * SEQ * DHEAD];
__device__ __nv_bfloat16 g_kl[(size_t)BHN * SEQ * DHEAD];
__device__ __nv_bfloat16 g_vh[(size_t)BHN * SEQ * DHEAD];
__device__ __nv_bfloat16 g_vl[(size_t)BHN * SEQ * DHEAD];

// ---------------- helpers ----------------
__device__ __forceinline__ void ldsm4(uint32_t* r, uint32_t addr) {
    asm volatile("ldmatrix.sync.aligned.m8n8.x4.shared.b16 {%0,%1,%2,%3}, [%4];"
                 : "=r"(r[0]), "=r"(r[1]), "=r"(r[2]), "=r"(r[3]) : "r"(addr));
}
__device__ __forceinline__ void ldsm4t(uint32_t* r, uint32_t addr) {
    asm volatile("ldmatrix.sync.aligned.m8n8.x4.trans.shared.b16 {%0,%1,%2,%3}, [%4];"
                 : "=r"(r[0]), "=r"(r[1]), "=r"(r[2]), "=r"(r[3]) : "r"(addr));
}
__device__ __forceinline__ void mma16816(float* d, const uint32_t* a,
                                         uint32_t b0, uint32_t b1) {
    asm volatile(
        "mma.sync.aligned.m16n8k16.row.col.f32.bf16.bf16.f32 "
        "{%0,%1,%2,%3}, {%4,%5,%6,%7}, {%8,%9}, {%0,%1,%2,%3};"
        : "+f"(d[0]), "+f"(d[1]), "+f"(d[2]), "+f"(d[3])
        : "r"(a[0]), "r"(a[1]), "r"(a[2]), "r"(a[3]), "r"(b0), "r"(b1));
}
__device__ __forceinline__ float ex2(float x) {
    float y; asm("ex2.approx.f32 %0, %1;" : "=f"(y) : "f"(x)); return y;
}
__device__ __forceinline__ uint32_t packbf(float lo, float hi) {
    uint32_t r; asm("cvt.rn.bf16x2.f32 %0, %1, %2;" : "=r"(r) : "f"(hi), "f"(lo));
    return r;
}

// ---------------------------------------------------------------------------
// RoPE table (fp32 angle, fp64 sin/cos)
// ---------------------------------------------------------------------------
__global__ void rope_table_kernel() {
    int p = blockIdx.x;
    int i = threadIdx.x;  // 0..63
    float freq = (float)pow(10000.0, (double)i / 64.0);
    float ang  = (float)p / freq;
    double s, c;
    sincos((double)ang, &s, &c);
    g_rope[p * 64 + i] = make_float2((float)s, (float)c);
}

// ---------------------------------------------------------------------------
// Rope + bf16 hi/lo split for q (QSCALE folded) and k.
// ---------------------------------------------------------------------------
__global__ void rope_split_kernel() {
    int gid = blockIdx.x * 256 + threadIdx.x;
    int i    = gid & 63;
    int rest = gid >> 6;
    int p    = rest & 2047;
    int bh   = rest >> 11;
    float2 sc = g_rope[p * 64 + i];
    size_t base = ((size_t)bh * SEQ + p) * DHEAD;

    float x0 = g_q[base + i], x1 = g_q[base + 64 + i];
    float q0 = (x0 * sc.y - x1 * sc.x) * QSCALE;
    float q1 = (x1 * sc.y + x0 * sc.x) * QSCALE;
    float y0 = g_k[base + i], y1 = g_k[base + 64 + i];
    float k0 = y0 * sc.y - y1 * sc.x;
    float k1 = y1 * sc.y + y0 * sc.x;

    __nv_bfloat16 h;
    h = __float2bfloat16(q0); g_qh[base + i]      = h; g_ql[base + i]      = __float2bfloat16(q0 - __bfloat162float(h));
    h = __float2bfloat16(q1); g_qh[base + 64 + i] = h; g_ql[base + 64 + i] = __float2bfloat16(q1 - __bfloat162float(h));
    h = __float2bfloat16(k0); g_kh[base + i]      = h; g_kl[base + i]      = __float2bfloat16(k0 - __bfloat162float(h));
    h = __float2bfloat16(k1); g_kh[base + 64 + i] = h; g_kl[base + 64 + i] = __float2bfloat16(k1 - __bfloat162float(h));
}

// ---------------------------------------------------------------------------
// fp32 -> (bf16 hi, bf16 lo) split, elementwise.
// ---------------------------------------------------------------------------
__global__ void split_kernel(const float* __restrict__ x,
                             __nv_bfloat16* __restrict__ hi,
                             __nv_bfloat16* __restrict__ lo) {
    size_t i = ((size_t)blockIdx.x * 256 + threadIdx.x) * 4;
    float4 v = *(const float4*)(x + i);
    float a[4] = {v.x, v.y, v.z, v.w};
    uint32_t ph[2], pl[2];
#pragma unroll
    for (int j = 0; j < 2; ++j) {
        __nv_bfloat16 h0 = __float2bfloat16(a[2*j]);
        __nv_bfloat16 h1 = __float2bfloat16(a[2*j+1]);
        __nv_bfloat16 l0 = __float2bfloat16(a[2*j]   - __bfloat162float(h0));
        __nv_bfloat16 l1 = __float2bfloat16(a[2*j+1] - __bfloat162float(h1));
        ph[j] = (uint32_t)__bfloat16_as_ushort(h0) | ((uint32_t)__bfloat16_as_ushort(h1) << 16);
        pl[j] = (uint32_t)__bfloat16_as_ushort(l0) | ((uint32_t)__bfloat16_as_ushort(l1) << 16);
    }
    *(uint2*)((char*)hi + i * 2) = make_uint2(ph[0], ph[1]);
    *(uint2*)((char*)lo + i * 2) = make_uint2(pl[0], pl[1]);
}

// ---------------------------------------------------------------------------
// Transpose + split: src [H][R][C] fp32 -> dst[h*C + c][r] bf16 (hi, lo).
// ---------------------------------------------------------------------------
__global__ void transpose_split_kernel(const float* __restrict__ src,
                                       __nv_bfloat16* __restrict__ hi,
                                       __nv_bfloat16* __restrict__ lo,
                                       int R, int C) {
    __shared__ float t[32][33];
    int h  = blockIdx.z;
    int r0 = blockIdx.y << 5, c0 = blockIdx.x << 5;
    int tx = threadIdx.x, ty = threadIdx.y;  // 32 x 8
    const float* s = src + (size_t)h * R * C;
#pragma unroll
    for (int j = 0; j < 4; ++j)
        t[ty + 8 * j][tx] = s[(size_t)(r0 + ty + 8 * j) * C + c0 + tx];
    __syncthreads();
#pragma unroll
    for (int j = 0; j < 4; ++j) {
        int c = c0 + ty + 8 * j;
        float v = t[tx][ty + 8 * j];
        __nv_bfloat16 vh = __float2bfloat16(v);
        __nv_bfloat16 vl = __float2bfloat16(v - __bfloat162float(vh));
        size_t o = (size_t)(h * C + c) * R + r0 + tx;
        hi[o] = vh;
        lo[o] = vl;
    }
}

// ---------------------------------------------------------------------------
// HMMA split GEMM: out = A * B^T + bias. Single-buffer KBLK=64,
// 4 warps (2m x 2n), warp tile 64x64, 128 threads, 2 CTAs/SM.
// mode 0: fp32 out -> [b][h][p][e]; mode 1: fp32 row-major;
// mode 2: bf16 hi/lo split out -> outh/outl at [b][h][p][e]  (V path).
// ---------------------------------------------------------------------------
__global__ __launch_bounds__(128, 2) void gemm_hmma(
    const __nv_bfloat16* __restrict__ Ah,
    const __nv_bfloat16* __restrict__ Al,
    const __nv_bfloat16* __restrict__ Bh,
    const __nv_bfloat16* __restrict__ Bl,
    const float* __restrict__ bias,
    float* __restrict__ out,
    __nv_bfloat16* __restrict__ outh,
    __nv_bfloat16* __restrict__ outl,
    int mode)
{
    extern __shared__ char sm[];
    const uint32_t sb = (uint32_t)__cvta_generic_to_shared(sm);

    const int tid  = threadIdx.x;
    const int wid  = tid >> 5;
    const int lane = tid & 31;
    const int row0 = blockIdx.y * 128;
    const int n0   = blockIdx.x * 128;
    const int m_w  = (wid & 1) * 64;
    const int n_w  = (wid >> 1) * 64;

    // ldmatrix per-lane bases
    const uint32_t aOff = (uint32_t)(m_w + (lane & 15)) * 144 + ((lane >> 4) << 4);
    const uint32_t bOff = (uint32_t)(n_w + ((lane >> 4) << 3) + (lane & 7)) * 144 +
                          (uint32_t)((lane & 8) << 1);
    const uint32_t aHi = sb + OFF_AH + aOff;
    const uint32_t aLo = sb + OFF_AL + aOff;
    const uint32_t bHi = sb + OFF_BH + bOff;
    const uint32_t bLo = sb + OFF_BL + bOff;

    float acc[4][8][4];
#pragma unroll
    for (int i = 0; i < 4; ++i)
#pragma unroll
        for (int j = 0; j < 8; ++j)
#pragma unroll
            for (int r = 0; r < 4; ++r) acc[i][j][r] = 0.0f;

    // gmem load indexing: 128 threads, per array 128 rows x 8 float4
    const int lr  = tid >> 3;          // 0..15 (+16 per i)
    const int lc8 = (tid & 7) * 8;     // 0..56

    for (int it = 0; it < DMODEL / 64; ++it) {
        const int k0 = it * 64;
        __syncthreads();
#pragma unroll
        for (int i = 0; i < 8; ++i) {
            int r = lr + i * 16;
            size_t ga = (size_t)(row0 + r) * DMODEL + k0 + lc8;
            size_t gb = (size_t)(n0 + r) * DMODEL + k0 + lc8;
            uint32_t so = (uint32_t)(r * 144 + lc8 * 2);
            *(float4*)(sm + OFF_AH + so) = *(const float4*)(Ah + ga);
            *(float4*)(sm + OFF_AL + so) = *(const float4*)(Al + ga);
            *(float4*)(sm + OFF_BH + so) = *(const float4*)(Bh + gb);
            *(float4*)(sm + OFF_BL + so) = *(const float4*)(Bl + gb);
        }
        __syncthreads();

#pragma unroll
        for (int kk = 0; kk < 4; ++kk) {
            uint32_t Af[4][4], Bf[4][4];
            // pass 1: Ah * Bh
#pragma unroll
            for (int mi = 0; mi < 4; ++mi)
                ldsm4(Af[mi], aHi + mi * (16 * 144) + kk * 32);
#pragma unroll
            for (int ni = 0; ni < 4; ++ni)
                ldsm4(Bf[ni], bHi + ni * (16 * 144) + kk * 32);
#pragma unroll
            for (int mi = 0; mi < 4; ++mi)
#pragma unroll
                for (int j = 0; j < 8; ++j)
                    mma16816(acc[mi][j], Af[mi], Bf[j >> 1][(j & 1) * 2],
                             Bf[j >> 1][(j & 1) * 2 + 1]);
            // pass 2: Al * Bh (reuse Bf)
            {
                uint32_t Al4[4];
#pragma unroll
                for (int mi = 0; mi < 4; ++mi) {
                    ldsm4(Al4, aLo + mi * (16 * 144) + kk * 32);
#pragma unroll
                    for (int j = 0; j < 8; ++j)
                        mma16816(acc[mi][j], Al4, Bf[j >> 1][(j & 1) * 2],
                                 Bf[j >> 1][(j & 1) * 2 + 1]);
                }
            }
            // pass 3: Ah * Bl (reuse Af)
#pragma unroll
            for (int ni = 0; ni < 4; ++ni)
                ldsm4(Bf[ni], bLo + ni * (16 * 144) + kk * 32);
#pragma unroll
            for (int mi = 0; mi < 4; ++mi)
#pragma unroll
                for (int j = 0; j < 8; ++j)
                    mma16816(acc[mi][j], Af[mi], Bf[j >> 1][(j & 1) * 2],
                             Bf[j >> 1][(j & 1) * 2 + 1]);
        }
    }

    // Epilogue
    const int g = lane >> 2, t4 = lane & 3;
#pragma unroll
    for (int mi = 0; mi < 4; ++mi) {
        int m = row0 + m_w + mi * 16 + g;
#pragma unroll
        for (int j = 0; j < 8; ++j) {
            int col = n0 + n_w + j * 8 + t4 * 2;
            float b0 = bias[col], b1 = bias[col + 1];
            float2 v0 = make_float2(acc[mi][j][0] + b0, acc[mi][j][1] + b1);
            float2 v1 = make_float2(acc[mi][j][2] + b0, acc[mi][j][3] + b1);
            if (mode == 1) {
                *(float2*)(out + (size_t)m * DMODEL + col)       = v0;
                *(float2*)(out + (size_t)(m + 8) * DMODEL + col) = v1;
            } else {
                int h = col >> 7, e = col & 127;
                int b  = m >> 11, p = m & 2047;
                size_t base = (((size_t)(b * NHEADS + h) * SEQ) << 7) + e;
                size_t i0 = base + ((size_t)p << 7);
                size_t i1 = base + ((size_t)(p + 8) << 7);
                if (mode == 0) {
                    *(float2*)(out + i0) = v0;
                    *(float2*)(out + i1) = v1;
                } else {  // mode 2: bf16 hi/lo split (V path)
                    uint32_t h0 = packbf(v0.x, v0.y);
                    uint32_t l0 = packbf(v0.x - __uint_as_float(h0 << 16),
                                         v0.y - __uint_as_float(h0 & 0xffff0000u));
                    uint32_t h1 = packbf(v1.x, v1.y);
                    uint32_t l1 = packbf(v1.x - __uint_as_float(h1 << 16),
                                         v1.y - __uint_as_float(h1 & 0xffff0000u));
                    *(uint32_t*)(outh + i0) = h0;
                    *(uint32_t*)(outl + i0) = l0;
                    *(uint32_t*)(outh + i1) = h1;
                    *(uint32_t*)(outl + i1) = l1;
                }
            }
        }
    }
}

// ---------------------------------------------------------------------------
// HMMA causal flash attention. CTA = 128 q x 128 kv, 8 warps x 16 rows.
// Epilogue writes z directly as bf16 hi/lo into g_ah/g_al (O-proj input).
// ---------------------------------------------------------------------------
__global__ __launch_bounds__(256, 1) void flash_hmma() {
    extern __shared__ char sm[];
    const uint32_t sb = (uint32_t)__cvta_generic_to_shared(sm);

    const int tid  = threadIdx.x;
    const int wid  = tid >> 5;
    const int lane = tid & 31;
    const int bh   = blockIdx.y;
    const int qt   = gridDim.x - 1 - blockIdx.x;   // heavy tiles first
    const int q0   = qt * 128;

    const __nv_bfloat16* qh = g_qh + (size_t)bh * SEQ * DHEAD;
    const __nv_bfloat16* ql = g_ql + (size_t)bh * SEQ * DHEAD;
    const __nv_bfloat16* kh = g_kh + (size_t)bh * SEQ * DHEAD;
    const __nv_bfloat16* kl = g_kl + (size_t)bh * SEQ * DHEAD;
    const __nv_bfloat16* vh = g_vh + (size_t)bh * SEQ * DHEAD;
    const __nv_bfloat16* vl = g_vl + (size_t)bh * SEQ * DHEAD;

#pragma unroll
    for (int i = 0; i < 8; ++i) {
        int f = tid + i * 256;
        int r = f >> 4, c8 = (f & 15) * 8;
        uint32_t off = (uint32_t)(r * FS + c8 * 2);
        size_t g = (size_t)(q0 + r) * DHEAD + c8;
        *(uint4*)(sm + FQH + off) = *(const uint4*)(qh + g);
        *(uint4*)(sm + FQL + off) = *(const uint4*)(ql + g);
    }

    const uint32_t aOff = (uint32_t)(wid * 16 + (lane & 15)) * FS + ((lane >> 4) << 4);
    const uint32_t aQh = sb + FQH + aOff;
    const uint32_t aQl = sb + FQL + aOff;
    const uint32_t bOff = (uint32_t)(((lane >> 4) << 3) + (lane & 7)) * FS +
                          (uint32_t)((lane & 8) << 1);
    const uint32_t bKh = sb + FKH + bOff;
    const uint32_t bKl = sb + FKL + bOff;
    const uint32_t vOff = (uint32_t)(lane & 15) * FS + ((lane >> 4) << 4);
    const uint32_t bVh = sb + FVH + vOff;
    const uint32_t bVl = sb + FVL + vOff;

    float o[16][4];
#pragma unroll
    for (int j = 0; j < 16; ++j)
#pragma unroll
        for (int r = 0; r < 4; ++r) o[j][r] = 0.0f;
    float m1 = -1e30f, m2 = -1e30f, l1 = 0.0f, l2 = 0.0f;

    for (int t = 0; t <= qt; ++t) {
        const int k0 = t * 128;
        __syncthreads();
#pragma unroll
        for (int i = 0; i < 8; ++i) {
            int f = tid + i * 256;
            int r = f >> 4, c8 = (f & 15) * 8;
            uint32_t off = (uint32_t)(r * FS + c8 * 2);
            size_t g = (size_t)(k0 + r) * DHEAD + c8;
            *(uint4*)(sm + FKH + off) = *(const uint4*)(kh + g);
            *(uint4*)(sm + FKL + off) = *(const uint4*)(kl + g);
            *(uint4*)(sm + FVH + off) = *(const uint4*)(vh + g);
            *(uint4*)(sm + FVL + off) = *(const uint4*)(vl + g);
        }
        __syncthreads();

        float s[16][4];
#pragma unroll
        for (int j = 0; j < 16; ++j)
#pragma unroll
            for (int r = 0; r < 4; ++r) s[j][r] = 0.0f;

#pragma unroll
        for (int kk = 0; kk < 8; ++kk) {
            uint32_t qa[4], qb[4], kb[4];
            ldsm4(qa, aQh + kk * 32);
            ldsm4(qb, aQl + kk * 32);
#pragma unroll
            for (int nn = 0; nn < 8; ++nn) {
                ldsm4(kb, bKh + nn * (16 * FS) + kk * 32);
                mma16816(s[2*nn],   qa, kb[0], kb[1]);
                mma16816(s[2*nn+1], qa, kb[2], kb[3]);
                mma16816(s[2*nn],   qb, kb[0], kb[1]);
                mma16816(s[2*nn+1], qb, kb[2], kb[3]);
                ldsm4(kb, bKl + nn * (16 * FS) + kk * 32);
                mma16816(s[2*nn],   qa, kb[0], kb[1]);
                mma16816(s[2*nn+1], qa, kb[2], kb[3]);
            }
        }

        const int r1 = q0 + wid * 16 + (lane >> 2);
        const int r2 = r1 + 8;
        if (t == qt) {
            const int c0 = k0 + (lane & 3) * 2;
#pragma unroll
            for (int j = 0; j < 16; ++j) {
                int col = c0 + j * 8;
                if (col     > r1) s[j][0] = -1e30f;
                if (col + 1 > r1) s[j][1] = -1e30f;
                if (col     > r2) s[j][2] = -1e30f;
                if (col + 1 > r2) s[j][3] = -1e30f;
            }
        }

        float mx1 = -1e30f, mx2 = -1e30f;
#pragma unroll
        for (int j = 0; j < 16; ++j) {
            mx1 = fmaxf(mx1, fmaxf(s[j][0], s[j][1]));
            mx2 = fmaxf(mx2, fmaxf(s[j][2], s[j][3]));
        }
        mx1 = fmaxf(mx1, __shfl_xor_sync(0xffffffffu, mx1, 1));
        mx1 = fmaxf(mx1, __shfl_xor_sync(0xffffffffu, mx1, 2));
        mx2 = fmaxf(mx2, __shfl_xor_sync(0xffffffffu, mx2, 1));
        mx2 = fmaxf(mx2, __shfl_xor_sync(0xffffffffu, mx2, 2));
        float mn1 = fmaxf(m1, mx1), mn2 = fmaxf(m2, mx2);
        float sc1 = ex2(m1 - mn1), sc2 = ex2(m2 - mn2);
        float rs1 = 0.0f, rs2 = 0.0f;
#pragma unroll
        for (int j = 0; j < 16; ++j) {
            s[j][0] = ex2(s[j][0] - mn1);
            s[j][1] = ex2(s[j][1] - mn1);
            s[j][2] = ex2(s[j][2] - mn2);
            s[j][3] = ex2(s[j][3] - mn2);
            rs1 += s[j][0] + s[j][1];
            rs2 += s[j][2] + s[j][3];
        }
        rs1 += __shfl_xor_sync(0xffffffffu, rs1, 1);
        rs1 += __shfl_xor_sync(0xffffffffu, rs1, 2);
        rs2 += __shfl_xor_sync(0xffffffffu, rs2, 1);
        rs2 += __shfl_xor_sync(0xffffffffu, rs2, 2);
        l1 = l1 * sc1 + rs1;  m1 = mn1;
        l2 = l2 * sc2 + rs2;  m2 = mn2;
#pragma unroll
        for (int j = 0; j < 16; ++j) {
            o[j][0] *= sc1; o[j][1] *= sc1;
            o[j][2] *= sc2; o[j][3] *= sc2;
        }

#pragma unroll
        for (int kk = 0; kk < 8; ++kk) {
            uint32_t ph[4], pl[4], vb[4];
#pragma unroll
            for (int hv = 0; hv < 2; ++hv) {
                const float* sp = s[2*kk + hv];
                uint32_t p0 = packbf(sp[0], sp[1]);
                uint32_t p1 = packbf(sp[2], sp[3]);
                ph[hv*2]   = p0;
                ph[hv*2+1] = p1;
                pl[hv*2]   = packbf(sp[0] - __uint_as_float(p0 << 16),
                                    sp[1] - __uint_as_float(p0 & 0xffff0000u));
                pl[hv*2+1] = packbf(sp[2] - __uint_as_float(p1 << 16),
                                    sp[3] - __uint_as_float(p1 & 0xffff0000u));
            }
            uint32_t pha[4] = {ph[0], ph[1], ph[2], ph[3]};
            uint32_t pla[4] = {pl[0], pl[1], pl[2], pl[3]};
#pragma unroll
            for (int nn = 0; nn < 8; ++nn) {
                ldsm4t(vb, bVh + kk * (16 * FS) + nn * 32);
                mma16816(o[2*nn],   pha, vb[0], vb[1]);
                mma16816(o[2*nn+1], pha, vb[2], vb[3]);
                mma16816(o[2*nn],   pla, vb[0], vb[1]);
                mma16816(o[2*nn+1], pla, vb[2], vb[3]);
                ldsm4t(vb, bVl + kk * (16 * FS) + nn * 32);
                mma16816(o[2*nn],   pha, vb[0], vb[1]);
                mma16816(o[2*nn+1], pha, vb[2], vb[3]);
            }
        }
    }

    // Epilogue: normalize + bf16 hi/lo split straight into g_ah/g_al.
    const int b = bh >> 4, h = bh & 15;
    const int r1 = q0 + wid * 16 + (lane >> 2);
    const float inv1 = 1.0f / l1, inv2 = 1.0f / l2;
    size_t base1 = (size_t)(b * SEQ + r1) * DMODEL + h * DHEAD + (lane & 3) * 2;
    size_t base2 = base1 + (size_t)8 * DMODEL;
#pragma unroll
    for (int j = 0; j < 16; ++j) {
        float a0 = o[j][0] * inv1, a1 = o[j][1] * inv1;
        uint32_t hh = packbf(a0, a1);
        uint32_t ll = packbf(a0 - __uint_as_float(hh << 16),
                             a1 - __uint_as_float(hh & 0xffff0000u));
        *(uint32_t*)&g_ah[base1 + j * 8] = hh;
        *(uint32_t*)&g_al[base1 + j * 8] = ll;
        float a2 = o[j][2] * inv2, a3 = o[j][3] * inv2;
        uint32_t hh2 = packbf(a2, a3);
        uint32_t ll2 = packbf(a2 - __uint_as_float(hh2 << 16),
                              a3 - __uint_as_float(hh2 & 0xffff0000u));
        *(uint32_t*)&g_ah[base2 + j * 8] = hh2;
        *(uint32_t*)&g_al[base2 + j * 8] = ll2;
    }
}

// ---------------------------------------------------------------------------
extern "C" void kernel_launch(void* const* d_in, const int* in_sizes, int n_in,
                              void* d_out, int out_size) {
    (void)in_sizes; (void)n_in; (void)out_size;
    const float* qin = (const float*)d_in[0];
    const float* kin = (const float*)d_in[1];
    const float* vin = (const float*)d_in[2];
    const float* WQ  = (const float*)d_in[3];
    const float* WK  = (const float*)d_in[4];
    const float* WV  = (const float*)d_in[5];
    const float* WO  = (const float*)d_in[6];
    const float* bQ  = (const float*)d_in[7];
    const float* bK  = (const float*)d_in[8];
    const float* bV  = (const float*)d_in[9];
    const float* bO  = (const float*)d_in[10];
    float* out = (float*)d_out;

    float *pq, *pk;
    __nv_bfloat16 *ah, *al, *wqh, *wql, *wkh, *wkl, *wvh, *wvl, *woh, *wol, *vh, *vl;
    cudaGetSymbolAddress((void**)&pq, g_q);
    cudaGetSymbolAddress((void**)&pk, g_k);
    cudaGetSymbolAddress((void**)&ah, g_ah);
    cudaGetSymbolAddress((void**)&al, g_al);
    cudaGetSymbolAddress((void**)&wqh, g_wqh);
    cudaGetSymbolAddress((void**)&wql, g_wql);
    cudaGetSymbolAddress((void**)&wkh, g_wkh);
    cudaGetSymbolAddress((void**)&wkl, g_wkl);
    cudaGetSymbolAddress((void**)&wvh, g_wvh);
    cudaGetSymbolAddress((void**)&wvl, g_wvl);
    cudaGetSymbolAddress((void**)&woh, g_woh);
    cudaGetSymbolAddress((void**)&wol, g_wol);
    cudaGetSymbolAddress((void**)&vh, g_vh);
    cudaGetSymbolAddress((void**)&vl, g_vl);

    cudaFuncSetAttribute((const void*)gemm_hmma,
                         cudaFuncAttributeMaxDynamicSharedMemorySize, GEMM_SMEM);
    cudaFuncSetAttribute((const void*)flash_hmma,
                         cudaFuncAttributeMaxDynamicSharedMemorySize, FLASH_SMEM);

    rope_table_kernel<<<SEQ, 64>>>();

    dim3 tb(32, 8);
    transpose_split_kernel<<<dim3(4, 64, 16), tb>>>(WQ, wqh, wql, DMODEL, DHEAD);
    transpose_split_kernel<<<dim3(4, 64, 16), tb>>>(WK, wkh, wkl, DMODEL, DHEAD);
    transpose_split_kernel<<<dim3(4, 64, 16), tb>>>(WV, wvh, wvl, DMODEL, DHEAD);
    transpose_split_kernel<<<dim3(64, 64, 1), tb>>>(WO, woh, wol, DMODEL, DMODEL);

    dim3 ggrid(DMODEL / 128, MROWS / 128);   // (16, 32)
    const int nsplit = (MROWS * DMODEL) / (256 * 4);

    split_kernel<<<nsplit, 256>>>(qin, ah, al);
    gemm_hmma<<<ggrid, 128, GEMM_SMEM>>>(ah, al, wqh, wql, bQ, pq, 0, 0, 0);
    split_kernel<<<nsplit, 256>>>(kin, ah, al);
    gemm_hmma<<<ggrid, 128, GEMM_SMEM>>>(ah, al, wkh, wkl, bK, pk, 0, 0, 0);
    split_kernel<<<nsplit, 256>>>(vin, ah, al);
    gemm_hmma<<<ggrid, 128, GEMM_SMEM>>>(ah, al, wvh, wvl, bV, 0, vh, vl, 2);

    rope_split_kernel<<<(BHN * SEQ * 64) / 256, 256>>>();

    flash_hmma<<<dim3(SEQ / 128, BHN), 256, FLASH_SMEM>>>();  // -> g_ah/g_al

    gemm_hmma<<<ggrid, 128, GEMM_SMEM>>>(ah, al, woh, wol, bO, out, 0, 0, 1);
}